// round 2
// baseline (speedup 1.0000x reference)
#include <cuda_runtime.h>
#include <cstdint>

#define NCAP 32
#define DCAP 64
#define BATCH 64
#define INCAP 1024
#define IDIM 256
#define NOUT (NCAP * DCAP)        // 2048
#define CHUNKS 16                 // 1024 / 64 i-values per fused block
#define ILEN 64

// ---------------- scratch (static device memory: no allocations) -------------
__device__ float g_uhat[(size_t)BATCH * NCAP * INCAP * DCAP]; // 512 MB, [b,n,i,dc]
__device__ float g_o[BATCH * NCAP * DCAP];                    // current normalized o
__device__ float g_opart[BATCH * CHUNKS * NCAP * DCAP];       // partial o per chunk

// ---------------- helpers ----------------------------------------------------
__device__ __forceinline__ uint32_t f2tf32(float x) {
    uint32_t r;
    asm("cvt.rna.tf32.f32 %0, %1;" : "=r"(r) : "f"(x));
    return r;
}

__device__ __forceinline__ void mma_tf32(float* d, const uint32_t* a, const uint32_t* b) {
    asm volatile(
        "mma.sync.aligned.m16n8k8.row.col.f32.tf32.tf32.f32 "
        "{%0,%1,%2,%3}, {%4,%5,%6,%7}, {%8,%9}, {%0,%1,%2,%3};"
        : "+f"(d[0]), "+f"(d[1]), "+f"(d[2]), "+f"(d[3])
        : "r"(a[0]), "r"(a[1]), "r"(a[2]), "r"(a[3]), "r"(b[0]), "r"(b[1]));
}

// ---------------- GEMM: u_hat[b,n,i,dc] = sum_d u[b,i,d] * W[n*64+dc, d] -----
// A = u_vecs [65536, 256] row-major, B = W [2048, 256] row-major (row.col fit).
// Block tile 128x128, K-tile 32, 8 warps (2 m x 4 n), warp tile 64x32.
__global__ void __launch_bounds__(256) gemm_kernel(const float* __restrict__ A,
                                                   const float* __restrict__ W) {
    constexpr int BM = 128, BN = 128, BK = 32, LDS_K = BK + 4; // stride 36: conflict-free frags
    __shared__ uint32_t As[BM][LDS_K];
    __shared__ uint32_t Bs[BN][LDS_K];

    const int tid  = threadIdx.x;
    const int warp = tid >> 5, lane = tid & 31;
    const int g = lane >> 2, tig = lane & 3;
    const int warpM = warp & 1;        // 0..1  -> 64 rows each
    const int warpN = warp >> 1;       // 0..3  -> 32 cols each
    const int m0 = blockIdx.y * BM;
    const int n0 = blockIdx.x * BN;

    float acc[4][4][4];
#pragma unroll
    for (int a = 0; a < 4; a++)
#pragma unroll
        for (int b = 0; b < 4; b++)
#pragma unroll
            for (int c = 0; c < 4; c++) acc[a][b][c] = 0.f;

    for (int k0 = 0; k0 < IDIM; k0 += BK) {
#pragma unroll
        for (int r = 0; r < 4; r++) {
            int idx = tid + r * 256;     // 0..1023
            int row = idx >> 3;          // 8 float4 per row of 32 floats
            int c4  = idx & 7;
            float4 va = *(const float4*)(A + (size_t)(m0 + row) * IDIM + k0 + c4 * 4);
            uint4 pa;
            pa.x = f2tf32(va.x); pa.y = f2tf32(va.y); pa.z = f2tf32(va.z); pa.w = f2tf32(va.w);
            *(uint4*)&As[row][c4 * 4] = pa;
            float4 vb = *(const float4*)(W + (size_t)(n0 + row) * IDIM + k0 + c4 * 4);
            uint4 pb;
            pb.x = f2tf32(vb.x); pb.y = f2tf32(vb.y); pb.z = f2tf32(vb.z); pb.w = f2tf32(vb.w);
            *(uint4*)&Bs[row][c4 * 4] = pb;
        }
        __syncthreads();

#pragma unroll
        for (int kk = 0; kk < BK; kk += 8) {
            uint32_t afr[4][4], bfr[4][2];
#pragma unroll
            for (int mt = 0; mt < 4; mt++) {
                int r = warpM * 64 + mt * 16 + g;
                afr[mt][0] = As[r][kk + tig];
                afr[mt][1] = As[r + 8][kk + tig];
                afr[mt][2] = As[r][kk + tig + 4];
                afr[mt][3] = As[r + 8][kk + tig + 4];
            }
#pragma unroll
            for (int nt = 0; nt < 4; nt++) {
                int nr = warpN * 32 + nt * 8 + g;
                bfr[nt][0] = Bs[nr][kk + tig];
                bfr[nt][1] = Bs[nr][kk + tig + 4];
            }
#pragma unroll
            for (int mt = 0; mt < 4; mt++)
#pragma unroll
                for (int nt = 0; nt < 4; nt++)
                    mma_tf32(acc[mt][nt], afr[mt], bfr[nt]);
        }
        __syncthreads();
    }

    // epilogue: scatter into [b,n,i,dc]; block spans a single batch b
    const int bb = m0 >> 10;
    const int ibase = m0 & 1023;
#pragma unroll
    for (int mt = 0; mt < 4; mt++) {
        int rlo = warpM * 64 + mt * 16 + g;
#pragma unroll
        for (int nt = 0; nt < 4; nt++) {
            int col = n0 + warpN * 32 + nt * 8 + 2 * tig;
            int n  = col >> 6;
            int dc = col & 63;
            size_t base = (((size_t)bb * NCAP + n) * INCAP + (ibase + rlo)) * DCAP + dc;
            float2 v01 = make_float2(acc[mt][nt][0], acc[mt][nt][1]);
            *(float2*)&g_uhat[base] = v01;
            float2 v23 = make_float2(acc[mt][nt][2], acc[mt][nt][3]);
            *(float2*)&g_uhat[base + (size_t)8 * DCAP] = v23;
        }
    }
}

// ---------------- routing iter 0: o0 = normalize( (1/32) * sum_i u_hat ) ----
__global__ void __launch_bounds__(256) init_o_kernel() {
    const int bn = blockIdx.x;                    // b*32 + n
    const float* base = g_uhat + (size_t)bn * (INCAP * DCAP);
    const int t = threadIdx.x;
    const int dc = t & 63, isub = t >> 6;

    float acc = 0.f;
#pragma unroll 8
    for (int i = isub; i < INCAP; i += 4)
        acc += base[(size_t)i * DCAP + dc];

    __shared__ float sm[256];
    sm[t] = acc;
    __syncthreads();

    float o_raw = 0.f;
    if (t < 64)
        o_raw = (sm[t] + sm[t + 64] + sm[t + 128] + sm[t + 192]) * (1.0f / 32.0f);

    float p = (t < 64) ? o_raw * o_raw : 0.f;
#pragma unroll
    for (int off = 16; off; off >>= 1) p += __shfl_xor_sync(0xffffffffu, p, off);

    __shared__ float red[8];
    if ((t & 31) == 0) red[t >> 5] = p;
    __syncthreads();
    float tot = red[0] + red[1];

    if (t < 64) {
        float norm = sqrtf(tot);
        g_o[bn * DCAP + t] = o_raw / fmaxf(norm, 1e-12f);
    }
}

// ---------------- fused pass: b = u_hat . o_prev ; c = softmax_n(b) ;
//                  o_part += c * u_hat   (single read of u_hat) ----------------
__global__ void __launch_bounds__(256) fused_kernel() {
    const int b = blockIdx.y;
    const int chunk = blockIdx.x;
    const int i0 = chunk * ILEN;
    const int t = threadIdx.x;
    const int w = t >> 5, l = t & 31;

    __shared__ float o_sh[NCAP * DCAP];   // [n][64]
    __shared__ float u_sh[NCAP * 65];     // [n][65] padded: conflict-free column reads
    __shared__ float s_sh[NCAP];
    __shared__ float c_sh[NCAP];

#pragma unroll
    for (int r = 0; r < 8; r++) {
        int idx = t + r * 256;
        o_sh[idx] = g_o[b * (NCAP * DCAP) + idx];
    }

    const int n_acc = t & 31;          // accumulation ownership: lane-distinct n
    const int d0 = (t >> 5) * 8;       // 8 d-values per thread
    float acc[8];
#pragma unroll
    for (int k = 0; k < 8; k++) acc[k] = 0.f;

    const float* ubase = g_uhat + (size_t)b * NCAP * INCAP * DCAP;
    const int ln0 = t >> 4,        lf0 = t & 15;          // slab-load mapping (256B/warp-half)
    const int ln1 = (t + 256) >> 4, lf1 = (t + 256) & 15;

    // prefetch slab i0
    float4 ra = *(const float4*)(ubase + ((size_t)ln0 * INCAP + i0) * DCAP + lf0 * 4);
    float4 rb = *(const float4*)(ubase + ((size_t)ln1 * INCAP + i0) * DCAP + lf1 * 4);
    __syncthreads();  // o_sh ready

    for (int ii = 0; ii < ILEN; ii++) {
        float* pa = &u_sh[ln0 * 65 + lf0 * 4];
        pa[0] = ra.x; pa[1] = ra.y; pa[2] = ra.z; pa[3] = ra.w;
        float* pb = &u_sh[ln1 * 65 + lf1 * 4];
        pb[0] = rb.x; pb[1] = rb.y; pb[2] = rb.z; pb[3] = rb.w;

        if (ii < ILEN - 1) {  // prefetch next slab; latency overlaps compute below
            int i = i0 + ii + 1;
            ra = *(const float4*)(ubase + ((size_t)ln0 * INCAP + i) * DCAP + lf0 * 4);
            rb = *(const float4*)(ubase + ((size_t)ln1 * INCAP + i) * DCAP + lf1 * 4);
        }
        __syncthreads();

        // logits b[n] = <u_hat[b,n,i,:], o[n,:]> ; warp w does n = w, w+8, w+16, w+24
#pragma unroll
        for (int q = 0; q < 4; q++) {
            int n = w + q * 8;
            float p = u_sh[n * 65 + l] * o_sh[n * 64 + l]
                    + u_sh[n * 65 + 32 + l] * o_sh[n * 64 + 32 + l];
#pragma unroll
            for (int off = 16; off; off >>= 1) p += __shfl_xor_sync(0xffffffffu, p, off);
            if (l == 0) s_sh[n] = p;
        }
        __syncthreads();

        // softmax over the 32 capsules (warp 0)
        if (t < 32) {
            float sv = s_sh[t];
            float m = sv;
#pragma unroll
            for (int off = 16; off; off >>= 1) m = fmaxf(m, __shfl_xor_sync(0xffffffffu, m, off));
            float e = __expf(sv - m);
            float s = e;
#pragma unroll
            for (int off = 16; off; off >>= 1) s += __shfl_xor_sync(0xffffffffu, s, off);
            c_sh[t] = e / s;
        }
        __syncthreads();

        // accumulate o_part[n] += c[n] * u_hat[b,n,i,:]
        const float cn = c_sh[n_acc];
        const float* up = &u_sh[n_acc * 65 + d0];
#pragma unroll
        for (int k = 0; k < 8; k++) acc[k] += cn * up[k];
        __syncthreads();  // protect u_sh before next overwrite
    }

    float* op = &g_opart[(((size_t)b * CHUNKS + chunk) * NCAP + n_acc) * DCAP + d0];
#pragma unroll
    for (int k = 0; k < 8; k++) op[k] = acc[k];
}

// ---------------- reduce partials; normalize (mid) or squash (last) ----------
template <int LAST>
__global__ void __launch_bounds__(64) reduce_kernel(float* __restrict__ out) {
    const int bn = blockIdx.x;                  // b*32 + n
    const int dc = threadIdx.x;                 // 0..63
    const int b = bn >> 5, n = bn & 31;

    float s = 0.f;
#pragma unroll
    for (int ch = 0; ch < CHUNKS; ch++)
        s += g_opart[(((size_t)b * CHUNKS + ch) * NCAP + n) * DCAP + dc];

    float p = s * s;
#pragma unroll
    for (int off = 16; off; off >>= 1) p += __shfl_xor_sync(0xffffffffu, p, off);

    __shared__ float red[2];
    if ((dc & 31) == 0) red[dc >> 5] = p;
    __syncthreads();
    float tot = red[0] + red[1];

    if (LAST) {
        float sq = tot + 1e-7f;
        float scale = sqrtf(sq) / (0.5f + sq);
        out[bn * DCAP + dc] = scale * s;
    } else {
        float norm = sqrtf(tot);
        g_o[bn * DCAP + dc] = s / fmaxf(norm, 1e-12f);
    }
}

// ---------------- launch ------------------------------------------------------
extern "C" void kernel_launch(void* const* d_in, const int* in_sizes, int n_in,
                              void* d_out, int out_size) {
    (void)in_sizes; (void)n_in; (void)out_size;
    const float* u = (const float*)d_in[0];   // [64, 1024, 256]
    const float* W = (const float*)d_in[1];   // [2048, 256]
    float* out = (float*)d_out;               // [64, 32, 64]

    gemm_kernel<<<dim3(NOUT / 128, (BATCH * INCAP) / 128), 256>>>(u, W);
    init_o_kernel<<<BATCH * NCAP, 256>>>();                 // iter 0: o0
    fused_kernel<<<dim3(CHUNKS, BATCH), 256>>>();           // iter 1: b1, softmax, o1 partials
    reduce_kernel<0><<<BATCH * NCAP, 64>>>(out);            // o1 normalize
    fused_kernel<<<dim3(CHUNKS, BATCH), 256>>>();           // iter 2: b2, softmax, o2 partials
    reduce_kernel<1><<<BATCH * NCAP, 64>>>(out);            // squash -> out
}

// round 3
// speedup vs baseline: 1.7772x; 1.7772x over previous
#include <cuda_runtime.h>
#include <cuda_fp16.h>
#include <cstdint>

#define NCAP 32
#define DCAP 64
#define BATCH 64
#define INCAP 1024
#define IDIM 256
#define CHUNKS 16
#define ILEN 64

// ---------------- static scratch ---------------------------------------------
// u_hat stored as fp16 pairs (uint32 words): [b, n, i, d/2] -> 256 MB
__device__ uint32_t g_uhat_h[(size_t)BATCH * NCAP * INCAP * (DCAP / 2)];
__device__ float g_osum_part[512 * 2048];               // per-mblock column sums
__device__ float g_o[BATCH * NCAP * DCAP];              // current normalized o
__device__ float g_opart[BATCH * CHUNKS * NCAP * DCAP]; // partial o per chunk

// ---------------- helpers ----------------------------------------------------
__device__ __forceinline__ uint32_t pack_h2(float a, float b) {
    __half2 h = __floats2half2_rn(a, b);
    return *reinterpret_cast<uint32_t*>(&h);
}
__device__ __forceinline__ float2 unpack_h2(uint32_t w) {
    __half2 h = *reinterpret_cast<__half2*>(&w);
    return __half22float2(h);
}

__device__ __forceinline__ void mma_f16(float* d, const uint32_t* a, const uint32_t* b) {
    asm volatile(
        "mma.sync.aligned.m16n8k16.row.col.f32.f16.f16.f32 "
        "{%0,%1,%2,%3}, {%4,%5,%6,%7}, {%8,%9}, {%0,%1,%2,%3};"
        : "+f"(d[0]), "+f"(d[1]), "+f"(d[2]), "+f"(d[3])
        : "r"(a[0]), "r"(a[1]), "r"(a[2]), "r"(a[3]), "r"(b[0]), "r"(b[1]));
}

// ---------------- GEMM: u_hat = u @ W^T (fp16 mma, fp16 out, fused colsums) --
// A [65536,256] fp32, W [2048,256] fp32. Block 128x128, BK=32 (2 k16 steps).
__global__ void __launch_bounds__(256) gemm_kernel(const float* __restrict__ A,
                                                   const float* __restrict__ W) {
    constexpr int BM = 128, BN = 128, LDW = 20; // 16 kwords used + 4 pad
    __shared__ uint32_t As[BM * LDW];
    __shared__ uint32_t Bs[BN * LDW];
    __shared__ float colsum[BN];

    const int tid = threadIdx.x;
    const int warp = tid >> 5, lane = tid & 31;
    const int g = lane >> 2, tig = lane & 3;
    const int warpM = warp & 1, warpN = warp >> 1;
    const int m0 = blockIdx.y * BM;
    const int n0 = blockIdx.x * BN;

    if (tid < BN) colsum[tid] = 0.f;

    float acc[4][4][4];
#pragma unroll
    for (int a = 0; a < 4; a++)
#pragma unroll
        for (int b = 0; b < 4; b++)
#pragma unroll
            for (int c = 0; c < 4; c++) acc[a][b][c] = 0.f;

    // per-thread load coords (4 chunks of 256 threads cover 128 rows x 8 float4)
    int lrow[4], lc4[4];
#pragma unroll
    for (int r = 0; r < 4; r++) {
        int idx = tid + r * 256;
        lrow[r] = idx >> 3;
        lc4[r] = idx & 7;
    }

    uint2 pa[4], pb[4];
#pragma unroll
    for (int r = 0; r < 4; r++) {
        float4 va = *(const float4*)(A + (size_t)(m0 + lrow[r]) * IDIM + lc4[r] * 4);
        pa[r] = make_uint2(pack_h2(va.x, va.y), pack_h2(va.z, va.w));
        float4 vb = *(const float4*)(W + (size_t)(n0 + lrow[r]) * IDIM + lc4[r] * 4);
        pb[r] = make_uint2(pack_h2(vb.x, vb.y), pack_h2(vb.z, vb.w));
    }

    for (int k0 = 0; k0 < IDIM; k0 += 32) {
#pragma unroll
        for (int r = 0; r < 4; r++) {
            As[lrow[r] * LDW + lc4[r] * 2]     = pa[r].x;
            As[lrow[r] * LDW + lc4[r] * 2 + 1] = pa[r].y;
            Bs[lrow[r] * LDW + lc4[r] * 2]     = pb[r].x;
            Bs[lrow[r] * LDW + lc4[r] * 2 + 1] = pb[r].y;
        }
        if (k0 + 32 < IDIM) {
#pragma unroll
            for (int r = 0; r < 4; r++) {
                float4 va = *(const float4*)(A + (size_t)(m0 + lrow[r]) * IDIM + k0 + 32 + lc4[r] * 4);
                pa[r] = make_uint2(pack_h2(va.x, va.y), pack_h2(va.z, va.w));
                float4 vb = *(const float4*)(W + (size_t)(n0 + lrow[r]) * IDIM + k0 + 32 + lc4[r] * 4);
                pb[r] = make_uint2(pack_h2(vb.x, vb.y), pack_h2(vb.z, vb.w));
            }
        }
        __syncthreads();

#pragma unroll
        for (int ks = 0; ks < 2; ks++) {
            const int kw = ks * 8;
            uint32_t afr[4][4], bfr[4][2];
#pragma unroll
            for (int mt = 0; mt < 4; mt++) {
                int r = warpM * 64 + mt * 16;
                afr[mt][0] = As[(r + g) * LDW + kw + tig];
                afr[mt][1] = As[(r + 8 + g) * LDW + kw + tig];
                afr[mt][2] = As[(r + g) * LDW + kw + tig + 4];
                afr[mt][3] = As[(r + 8 + g) * LDW + kw + tig + 4];
            }
#pragma unroll
            for (int nt = 0; nt < 4; nt++) {
                int nr = warpN * 32 + nt * 8;
                bfr[nt][0] = Bs[(nr + g) * LDW + kw + tig];
                bfr[nt][1] = Bs[(nr + g) * LDW + kw + tig + 4];
            }
#pragma unroll
            for (int mt = 0; mt < 4; mt++)
#pragma unroll
                for (int nt = 0; nt < 4; nt++)
                    mma_f16(acc[mt][nt], afr[mt], bfr[nt]);
        }
        __syncthreads();
    }

    // epilogue: fp16 store + column sums
    const int bb = m0 >> 10;
    const int ibase = m0 & 1023;
    float s[4][2];
#pragma unroll
    for (int nt = 0; nt < 4; nt++) { s[nt][0] = 0.f; s[nt][1] = 0.f; }

#pragma unroll
    for (int mt = 0; mt < 4; mt++) {
        int rlo = warpM * 64 + mt * 16 + g;
#pragma unroll
        for (int nt = 0; nt < 4; nt++) {
            int col = n0 + warpN * 32 + nt * 8 + 2 * tig;
            int n = col >> 6, dc = col & 63;
            size_t widx = (((size_t)bb * NCAP + n) * INCAP + (ibase + rlo)) * (DCAP / 2) + (dc >> 1);
            g_uhat_h[widx] = pack_h2(acc[mt][nt][0], acc[mt][nt][1]);
            g_uhat_h[widx + 8 * (DCAP / 2)] = pack_h2(acc[mt][nt][2], acc[mt][nt][3]);
            s[nt][0] += acc[mt][nt][0] + acc[mt][nt][2];
            s[nt][1] += acc[mt][nt][1] + acc[mt][nt][3];
        }
    }
#pragma unroll
    for (int nt = 0; nt < 4; nt++) {
#pragma unroll
        for (int off = 4; off < 32; off <<= 1) {
            s[nt][0] += __shfl_xor_sync(0xffffffffu, s[nt][0], off);
            s[nt][1] += __shfl_xor_sync(0xffffffffu, s[nt][1], off);
        }
    }
    if (lane < 4) {
#pragma unroll
        for (int nt = 0; nt < 4; nt++) {
            int col = warpN * 32 + nt * 8 + 2 * lane;
            atomicAdd(&colsum[col], s[nt][0]);
            atomicAdd(&colsum[col + 1], s[nt][1]);
        }
    }
    __syncthreads();
    if (tid < BN)
        g_osum_part[(size_t)blockIdx.y * 2048 + n0 + tid] = colsum[tid];
}

// ---------------- iter 0: o0 = normalize(colsum) ------------------------------
__global__ void __launch_bounds__(64) init_o_kernel() {
    const int bn = blockIdx.x;             // b*32 + n
    const int b = bn >> 5, n = bn & 31;
    const int dc = threadIdx.x;

    float s = 0.f;
#pragma unroll
    for (int y = 0; y < 8; y++)
        s += g_osum_part[(size_t)(b * 8 + y) * 2048 + n * DCAP + dc];

    float p = s * s;
#pragma unroll
    for (int off = 16; off; off >>= 1) p += __shfl_xor_sync(0xffffffffu, p, off);
    __shared__ float red[2];
    if ((dc & 31) == 0) red[dc >> 5] = p;
    __syncthreads();
    float norm = sqrtf(red[0] + red[1]);
    g_o[bn * DCAP + dc] = s / fmaxf(norm, 1e-12f);
}

// ---------------- fused routing pass (fp16, 8 i-slabs per sync group) --------
// warp w owns slab j=w: lane l = capsule n; logits+softmax fully warp-local.
__global__ void __launch_bounds__(256) fused_kernel() {
    constexpr int UST = 33; // words per (j,n) row: 32 used + 1 pad
    const int b = blockIdx.y;
    const int i0 = blockIdx.x * ILEN;
    const int t = threadIdx.x;
    const int w = t >> 5, l = t & 31;

    __shared__ float o_sh[NCAP * 65];
    __shared__ uint32_t u_sh[256 * UST]; // rows (j*32+n)
    __shared__ float c_sh[8 * NCAP];

#pragma unroll
    for (int r = 0; r < 8; r++) {
        int idx = t + r * 256;
        o_sh[(idx >> 6) * 65 + (idx & 63)] = g_o[b * (NCAP * DCAP) + idx];
    }

    const int n_acc = t & 31;
    const int d0 = (t >> 5) * 8;
    float acc[8];
#pragma unroll
    for (int k = 0; k < 8; k++) acc[k] = 0.f;

    const uint32_t* ub = g_uhat_h + (size_t)b * NCAP * INCAP * (DCAP / 2);
    const int ln = t >> 3, lseg = t & 7; // thread loads row n=ln, 16B segment lseg

    uint4 pre[8];
#pragma unroll
    for (int j = 0; j < 8; j++)
        pre[j] = *(const uint4*)&ub[((size_t)ln * INCAP + i0 + j) * (DCAP / 2) + lseg * 4];
    __syncthreads();

    for (int grp = 0; grp < 8; grp++) {
#pragma unroll
        for (int j = 0; j < 8; j++) {
            uint32_t* p = &u_sh[(j * 32 + ln) * UST + lseg * 4];
            p[0] = pre[j].x; p[1] = pre[j].y; p[2] = pre[j].z; p[3] = pre[j].w;
        }
        if (grp < 7) {
            int ig = i0 + (grp + 1) * 8;
#pragma unroll
            for (int j = 0; j < 8; j++)
                pre[j] = *(const uint4*)&ub[((size_t)ln * INCAP + ig + j) * (DCAP / 2) + lseg * 4];
        }
        __syncthreads();

        // logits: warp w -> slab j=w, lane l -> capsule n=l
        {
            const uint32_t* up = &u_sh[(w * 32 + l) * UST];
            const float* op = &o_sh[l * 65];
            float dot = 0.f;
#pragma unroll
            for (int m = 0; m < 32; m++) {
                float2 u2 = unpack_h2(up[m]);
                dot += u2.x * op[2 * m] + u2.y * op[2 * m + 1];
            }
            float mx = dot;
#pragma unroll
            for (int off = 16; off; off >>= 1) mx = fmaxf(mx, __shfl_xor_sync(0xffffffffu, mx, off));
            float e = __expf(dot - mx);
            float sum = e;
#pragma unroll
            for (int off = 16; off; off >>= 1) sum += __shfl_xor_sync(0xffffffffu, sum, off);
            c_sh[w * 32 + l] = e / sum;
        }
        __syncthreads();

        // accumulate: thread (n_acc, d0..d0+7) over 8 slabs
#pragma unroll
        for (int j = 0; j < 8; j++) {
            float cn = c_sh[j * 32 + n_acc];
            const uint32_t* uq = &u_sh[(j * 32 + n_acc) * UST + (d0 >> 1)];
#pragma unroll
            for (int k = 0; k < 4; k++) {
                float2 u2 = unpack_h2(uq[k]);
                acc[2 * k] += cn * u2.x;
                acc[2 * k + 1] += cn * u2.y;
            }
        }
        __syncthreads();
    }

    float* op = &g_opart[(((size_t)b * CHUNKS + blockIdx.x) * NCAP + n_acc) * DCAP + d0];
    *(float4*)op = make_float4(acc[0], acc[1], acc[2], acc[3]);
    *(float4*)(op + 4) = make_float4(acc[4], acc[5], acc[6], acc[7]);
}

// ---------------- reduce partials; normalize (mid) or squash (last) ----------
template <int LAST>
__global__ void __launch_bounds__(64) reduce_kernel(float* __restrict__ out) {
    const int bn = blockIdx.x;
    const int dc = threadIdx.x;
    const int b = bn >> 5, n = bn & 31;

    float s = 0.f;
#pragma unroll
    for (int ch = 0; ch < CHUNKS; ch++)
        s += g_opart[(((size_t)b * CHUNKS + ch) * NCAP + n) * DCAP + dc];

    float p = s * s;
#pragma unroll
    for (int off = 16; off; off >>= 1) p += __shfl_xor_sync(0xffffffffu, p, off);
    __shared__ float red[2];
    if ((dc & 31) == 0) red[dc >> 5] = p;
    __syncthreads();
    float tot = red[0] + red[1];

    if (LAST) {
        float sq = tot + 1e-7f;
        float scale = sqrtf(sq) / (0.5f + sq);
        out[bn * DCAP + dc] = scale * s;
    } else {
        float norm = sqrtf(tot);
        g_o[bn * DCAP + dc] = s / fmaxf(norm, 1e-12f);
    }
}

// ---------------- launch ------------------------------------------------------
extern "C" void kernel_launch(void* const* d_in, const int* in_sizes, int n_in,
                              void* d_out, int out_size) {
    (void)in_sizes; (void)n_in; (void)out_size;
    const float* u = (const float*)d_in[0];
    const float* W = (const float*)d_in[1];
    float* out = (float*)d_out;

    gemm_kernel<<<dim3(2048 / 128, (BATCH * INCAP) / 128), 256>>>(u, W);
    init_o_kernel<<<BATCH * NCAP, 64>>>();              // iter 0 (colsums fused in GEMM)
    fused_kernel<<<dim3(CHUNKS, BATCH), 256>>>();       // iter 1
    reduce_kernel<0><<<BATCH * NCAP, 64>>>(out);
    fused_kernel<<<dim3(CHUNKS, BATCH), 256>>>();       // iter 2
    reduce_kernel<1><<<BATCH * NCAP, 64>>>(out);
}

// round 5
// speedup vs baseline: 3.1457x; 1.7700x over previous
#include <cuda_runtime.h>
#include <cstdint>

#define B 64
#define IN 1024
#define ID 256
#define NC 32
#define DC 64
#define CH 8      // i-chunks per batch in fused pass (128 i each)
#define GI 8      // i per sync group
#define GRPS 16   // groups per chunk

// ---------------- static scratch (18.5 MB total) -----------------------------
__device__ float g_spart[B * 8 * ID];          // colsum partials
__device__ float g_wtil[B * NC * ID];          // w~ = W_n^T o_n  (2 MB)
__device__ float g_vpart[B * CH * NC * ID];    // v partials (16 MB)

// ---------------- packed f32x2 fma (sm_100+ PTX) -----------------------------
typedef unsigned long long ull;
__device__ __forceinline__ void fma2(ull& d, ull a, ull b) {
    asm("fma.rn.f32x2 %0, %1, %2, %0;" : "+l"(d) : "l"(a), "l"(b));
}
__device__ __forceinline__ ull pack2(float2 v) { return *reinterpret_cast<ull*>(&v); }
__device__ __forceinline__ float2 unpk2(ull v) { return *reinterpret_cast<float2*>(&v); }

// ---------------- column sum: s[b,d] = sum_i u[b,i,d] ------------------------
__global__ void __launch_bounds__(256) colsum_kernel(const float* __restrict__ u) {
    const int s = blockIdx.x, b = blockIdx.y, d = threadIdx.x;
    const float* p = u + ((size_t)b * IN + s * 128) * ID + d;
    float a0 = 0.f, a1 = 0.f, a2 = 0.f, a3 = 0.f;
#pragma unroll 8
    for (int i = 0; i < 128; i += 4) {
        a0 += p[(size_t)i * ID];
        a1 += p[(size_t)(i + 1) * ID];
        a2 += p[(size_t)(i + 2) * ID];
        a3 += p[(size_t)(i + 3) * ID];
    }
    g_spart[(b * 8 + s) * ID + d] = (a0 + a1) + (a2 + a3);
}

// ---------------- projection: v -> o -> (normalize -> w~ | squash -> out) ----
// PHASE 0: input = colsum partials (iter0).  PHASE 1: input = vpart, emit w~.
// PHASE 2: input = vpart, squash, write output.
// Grid (n=32, bgroup=8); block 256; W_n cached in 64 KB dynamic smem.
template <int PHASE>
__global__ void __launch_bounds__(256) project_kernel(const float* __restrict__ W,
                                                      float* __restrict__ out) {
    extern __shared__ float Wsh[];            // [64][256]
    __shared__ float v_sh[ID];
    __shared__ float o_sh[DC];
    __shared__ float red_sh;

    const int n = blockIdx.x, bg = blockIdx.y;
    const int t = threadIdx.x, w = t >> 5, l = t & 31;

    for (int idx = t; idx < DC * ID; idx += 256)
        Wsh[idx] = W[(size_t)n * DC * ID + idx];
    __syncthreads();

    for (int bi = 0; bi < 8; bi++) {
        const int b = bg * 8 + bi;
        // gather v (or s) for this (b, n)
        float v = 0.f;
        if (PHASE == 0) {
#pragma unroll
            for (int s = 0; s < 8; s++) v += g_spart[(b * 8 + s) * ID + t];
            v *= (1.0f / 32.0f);
        } else {
#pragma unroll
            for (int c = 0; c < CH; c++) v += g_vpart[(((size_t)b * CH + c) * NC + n) * ID + t];
        }
        v_sh[t] = v;
        __syncthreads();

        // o_dc = <W_n[dc,:], v> ; warp w handles rows w*8..w*8+7
#pragma unroll
        for (int q = 0; q < 8; q++) {
            const int r = w * 8 + q;
            float p = 0.f;
#pragma unroll
            for (int m = 0; m < 8; m++) p += Wsh[r * ID + l + 32 * m] * v_sh[l + 32 * m];
#pragma unroll
            for (int off = 16; off; off >>= 1) p += __shfl_xor_sync(0xffffffffu, p, off);
            if (l == 0) o_sh[r] = p;
        }
        __syncthreads();

        // ||o||^2
        if (t < 32) {
            float p = o_sh[t] * o_sh[t] + o_sh[t + 32] * o_sh[t + 32];
#pragma unroll
            for (int off = 16; off; off >>= 1) p += __shfl_xor_sync(0xffffffffu, p, off);
            if (t == 0) red_sh = p;
        }
        __syncthreads();
        const float tot = red_sh;

        if (PHASE == 2) {
            if (t < DC) {
                float sq = tot + 1e-7f;
                float sc = sqrtf(sq) / (0.5f + sq);
                out[((size_t)b * NC + n) * DC + t] = sc * o_sh[t];
            }
        } else {
            // w~_d = inv_norm * sum_dc W_n[dc,d] * o_dc   (inv applied at end)
            const float inv = 1.0f / fmaxf(sqrtf(tot), 1e-12f);
            float acc = 0.f;
#pragma unroll
            for (int dc = 0; dc < DC; dc++) acc += Wsh[dc * ID + t] * o_sh[dc];
            g_wtil[((size_t)b * NC + n) * ID + t] = acc * inv;
        }
        __syncthreads();  // free v_sh / o_sh for next bi
    }
}

// ---------------- fused routing: logits + softmax + v accumulation -----------
// Grid (chunk=8, b=64); block 256. Thread role: n = lane, g = warp (32-d slice).
__global__ void __launch_bounds__(256) fused_kernel(const float* __restrict__ u) {
    __shared__ float u_sh[GI * ID];           // 8 KB  [j][256]
    __shared__ float part_sh[GI * 8 * NC];    // 8 KB  [j][g][n]
    __shared__ float c_sh[GI * NC];           // 1 KB  [j][n]

    const int chunk = blockIdx.x, b = blockIdx.y;
    const int t = threadIdx.x, w = t >> 5, l = t & 31;
    const int n = l, g = w;

    // this thread's w~ slice -> registers (n = lane, d in [g*32, g*32+32))
    ull wt2[16];
    {
        const float2* wp = (const float2*)&g_wtil[((size_t)b * NC + n) * ID + g * 32];
#pragma unroll
        for (int m = 0; m < 16; m++) wt2[m] = pack2(wp[m]);
    }

    ull acc2[16];
    {
        float2 z = make_float2(0.f, 0.f);
#pragma unroll
        for (int m = 0; m < 16; m++) acc2[m] = pack2(z);
    }

    const float* ub = u + ((size_t)b * IN + chunk * 128) * ID;

    // slab load mapping: warp w loads row j=w, lane l covers d = l*8..l*8+7
    float4 pre0 = *(const float4*)(ub + w * ID + l * 8);
    float4 pre1 = *(const float4*)(ub + w * ID + l * 8 + 4);

    for (int grp = 0; grp < GRPS; grp++) {
        *(float4*)&u_sh[w * ID + l * 8] = pre0;
        *(float4*)&u_sh[w * ID + l * 8 + 4] = pre1;
        if (grp < GRPS - 1) {
            const float* nx = ub + (size_t)(grp + 1) * GI * ID + w * ID + l * 8;
            pre0 = *(const float4*)nx;
            pre1 = *(const float4*)(nx + 4);
        }
        __syncthreads();

        // partial dots: thread (n, g) for each of 8 i's
#pragma unroll
        for (int j = 0; j < GI; j++) {
            float2 z = make_float2(0.f, 0.f);
            ull d2 = pack2(z);
            const float2* up = (const float2*)&u_sh[j * ID + g * 32];  // broadcast
#pragma unroll
            for (int m = 0; m < 16; m++) fma2(d2, pack2(up[m]), wt2[m]);
            float2 dd = unpk2(d2);
            part_sh[(j * 8 + g) * NC + n] = dd.x + dd.y;
        }
        __syncthreads();

        // softmax over n: warp j = w handles i-index j, lane = n
        {
            float dot = 0.f;
#pragma unroll
            for (int gg = 0; gg < 8; gg++) dot += part_sh[(w * 8 + gg) * NC + l];
            float mx = dot;
#pragma unroll
            for (int off = 16; off; off >>= 1)
                mx = fmaxf(mx, __shfl_xor_sync(0xffffffffu, mx, off));
            float e = __expf(dot - mx);
            float s = e;
#pragma unroll
            for (int off = 16; off; off >>= 1) s += __shfl_xor_sync(0xffffffffu, s, off);
            c_sh[w * NC + l] = e / s;
        }
        __syncthreads();

        // v accumulation: acc[n, g*32+k] += c[j][n] * u[j][g*32+k]
#pragma unroll
        for (int j = 0; j < GI; j++) {
            const float cn = c_sh[j * NC + n];
            ull c2 = pack2(make_float2(cn, cn));
            const float2* up = (const float2*)&u_sh[j * ID + g * 32];  // broadcast
#pragma unroll
            for (int m = 0; m < 16; m++) fma2(acc2[m], c2, pack2(up[m]));
        }
        __syncthreads();  // u_sh free for next group
    }

    float2* vp = (float2*)&g_vpart[(((size_t)b * CH + chunk) * NC + n) * ID + g * 32];
#pragma unroll
    for (int m = 0; m < 16; m++) vp[m] = unpk2(acc2[m]);
}

// ---------------- launch ------------------------------------------------------
extern "C" void kernel_launch(void* const* d_in, const int* in_sizes, int n_in,
                              void* d_out, int out_size) {
    (void)in_sizes; (void)n_in; (void)out_size;
    const float* u = (const float*)d_in[0];   // [64, 1024, 256] fp32
    const float* W = (const float*)d_in[1];   // [2048, 256] fp32
    float* out = (float*)d_out;               // [64, 32, 64] fp32

    const int wbytes = DC * ID * (int)sizeof(float);  // 64 KB dynamic smem
    static int attr_done = 0;
    if (!attr_done) {
        cudaFuncSetAttribute(project_kernel<0>, cudaFuncAttributeMaxDynamicSharedMemorySize, wbytes);
        cudaFuncSetAttribute(project_kernel<1>, cudaFuncAttributeMaxDynamicSharedMemorySize, wbytes);
        cudaFuncSetAttribute(project_kernel<2>, cudaFuncAttributeMaxDynamicSharedMemorySize, wbytes);
        attr_done = 1;
    }

    colsum_kernel<<<dim3(8, B), 256>>>(u);                       // s = sum_i u
    project_kernel<0><<<dim3(NC, 8), 256, wbytes>>>(W, out);     // o0 -> w~0
    fused_kernel<<<dim3(CH, B), 256>>>(u);                       // iter 1 -> v1
    project_kernel<1><<<dim3(NC, 8), 256, wbytes>>>(W, out);     // o1 -> w~1
    fused_kernel<<<dim3(CH, B), 256>>>(u);                       // iter 2 -> v2
    project_kernel<2><<<dim3(NC, 8), 256, wbytes>>>(W, out);     // squash -> out
}

// round 8
// speedup vs baseline: 4.9035x; 1.5588x over previous
#include <cuda_runtime.h>
#include <cuda_fp16.h>
#include <cstdint>

#define B 64
#define IN 1024
#define ID 256
#define NC 32
#define DC 64
#define IT 64           // i per fused block
#define CH (IN / IT)    // 16 chunks

// ---------------- static scratch ---------------------------------------------
__device__ __half g_wtil[B * NC * ID];                 // w~ fp16 (1 MB)
__device__ float  g_spart[B * 8 * ID];                 // colsum partials
__device__ float  g_vpart[(size_t)B * CH * NC * ID];   // v partials (32 MB)

// ---------------- mma helper (validated rounds 2-3) --------------------------
__device__ __forceinline__ void mma_f16(float* d, const uint32_t* a, const uint32_t* b) {
    asm volatile(
        "mma.sync.aligned.m16n8k16.row.col.f32.f16.f16.f32 "
        "{%0,%1,%2,%3}, {%4,%5,%6,%7}, {%8,%9}, {%0,%1,%2,%3};"
        : "+f"(d[0]), "+f"(d[1]), "+f"(d[2]), "+f"(d[3])
        : "r"(a[0]), "r"(a[1]), "r"(a[2]), "r"(a[3]), "r"(b[0]), "r"(b[1]));
}
__device__ __forceinline__ uint32_t h2u(__half2 h) { return *reinterpret_cast<uint32_t*>(&h); }

// ---------------- column sum: s[b,d] = sum_i u[b,i,d] ------------------------
__global__ void __launch_bounds__(256) colsum_kernel(const float* __restrict__ u) {
    const int s = blockIdx.x, b = blockIdx.y, d = threadIdx.x;
    const float* p = u + ((size_t)b * IN + s * 128) * ID + d;
    float a0 = 0.f, a1 = 0.f, a2 = 0.f, a3 = 0.f;
#pragma unroll 8
    for (int i = 0; i < 128; i += 4) {
        a0 += p[(size_t)i * ID];
        a1 += p[(size_t)(i + 1) * ID];
        a2 += p[(size_t)(i + 2) * ID];
        a3 += p[(size_t)(i + 3) * ID];
    }
    g_spart[(b * 8 + s) * ID + d] = (a0 + a1) + (a2 + a3);
}

// ---------------- projection: warp-per-batch, no inner block syncs -----------
// PHASE 0: v from colsum partials. PHASE 1: v from vpart -> w~. PHASE 2: squash.
template <int PHASE>
__global__ void __launch_bounds__(256) project_kernel(const float* __restrict__ W,
                                                      float* __restrict__ out) {
    extern __shared__ float Wsh[];            // [64][256] = 64 KB
    __shared__ float o_ws[8][DC];

    const int n = blockIdx.x, bg = blockIdx.y;
    const int t = threadIdx.x, w = t >> 5, l = t & 31;

    for (int idx = t; idx < DC * ID; idx += 256)
        Wsh[idx] = W[(size_t)n * DC * ID + idx];
    __syncthreads();

    const int b = bg * 8 + w;

    // gather v: lane l owns d = l + 32m
    float v[8];
    if (PHASE == 0) {
#pragma unroll
        for (int m = 0; m < 8; m++) {
            float s = 0.f;
#pragma unroll
            for (int q = 0; q < 8; q++) s += g_spart[(b * 8 + q) * ID + l + 32 * m];
            v[m] = s * (1.0f / 32.0f);
        }
    } else {
#pragma unroll
        for (int m = 0; m < 8; m++) v[m] = 0.f;
#pragma unroll 4
        for (int c = 0; c < CH; c++) {
            const float* pp = g_vpart + (((size_t)b * CH + c) * NC + n) * ID;
#pragma unroll
            for (int m = 0; m < 8; m++) v[m] += pp[l + 32 * m];
        }
    }

    // o_dc = <W_n[dc,:], v>
#pragma unroll
    for (int dc = 0; dc < DC; dc++) {
        float p = 0.f;
#pragma unroll
        for (int m = 0; m < 8; m++) p += Wsh[dc * ID + l + 32 * m] * v[m];
#pragma unroll
        for (int off = 16; off; off >>= 1) p += __shfl_xor_sync(0xffffffffu, p, off);
        if (l == 0) o_ws[w][dc] = p;
    }
    __syncwarp();

    float p2 = o_ws[w][l] * o_ws[w][l] + o_ws[w][32 + l] * o_ws[w][32 + l];
#pragma unroll
    for (int off = 16; off; off >>= 1) p2 += __shfl_xor_sync(0xffffffffu, p2, off);
    const float tot = p2;

    if (PHASE == 2) {
        float sq = tot + 1e-7f;
        float sc = sqrtf(sq) / (0.5f + sq);
        out[((size_t)b * NC + n) * DC + l] = sc * o_ws[w][l];
        out[((size_t)b * NC + n) * DC + 32 + l] = sc * o_ws[w][32 + l];
    } else {
        const float inv = 1.0f / fmaxf(sqrtf(tot), 1e-12f);
        float acc[8];
#pragma unroll
        for (int m = 0; m < 8; m++) acc[m] = 0.f;
#pragma unroll
        for (int dc = 0; dc < DC; dc++) {
            const float od = o_ws[w][dc];
#pragma unroll
            for (int m = 0; m < 8; m++) acc[m] += Wsh[dc * ID + l + 32 * m] * od;
        }
#pragma unroll
        for (int m = 0; m < 8; m++)
            g_wtil[((size_t)b * NC + n) * ID + l + 32 * m] = __float2half_rn(acc[m] * inv);
    }
}

// ---------------- fused routing: fp16 mma logits + fp16 mma accumulation -----
// Block: (b, chunk of 64 i). smem layout (bytes):
//   u_sh  half [64][264]   @0       (33792 B)  d-contiguous, row stride 132 words
//   u_t   half [256][66]   @33792   (33792 B)  i-contiguous, col-swizzled
//   w_sh  half [32][264]   @67584   (16896 B)
//   c_sh  half [32][72]    @84480   (4608 B)   i-contiguous
//   L_sh  float[64][34]    @89088   (8704 B)
__global__ void __launch_bounds__(256, 2) fused_kernel(const float* __restrict__ u) {
    extern __shared__ char smem[];
    __half* u_sh = (__half*)smem;
    __half* u_t = (__half*)(smem + 33792);
    __half* w_sh = (__half*)(smem + 67584);
    __half* c_sh = (__half*)(smem + 84480);
    float* L_sh = (float*)(smem + 89088);

    const int chunk = blockIdx.x, b = blockIdx.y;
    const int t = threadIdx.x, w = t >> 5, l = t & 31;
    const int g = l >> 2, tig = l & 3;

    // ---- load w~ (fp16 direct): thread: n = t>>3, seg = t&7 (32 d)
    {
        const int n = t >> 3, seg = t & 7;
        const uint4* wp = (const uint4*)(g_wtil + ((size_t)b * NC + n) * ID + seg * 32);
        uint4* ws = (uint4*)&w_sh[n * 264 + seg * 32];
        ws[0] = wp[0]; ws[1] = wp[1]; ws[2] = wp[2]; ws[3] = wp[3];
    }

    // ---- load u tile (fp32 -> fp16 into BOTH layouts)
    {
        const int ipair = t >> 3, seg = t & 7;
        const float* up = u + ((size_t)b * IN + chunk * IT + ipair * 2) * ID + seg * 32;
        float4 r0[8], r1[8];
#pragma unroll
        for (int q = 0; q < 8; q++) r0[q] = ((const float4*)up)[q];
#pragma unroll
        for (int q = 0; q < 8; q++) r1[q] = ((const float4*)(up + ID))[q];

        // u_sh rows 2*ipair, 2*ipair+1 (d-contiguous)
#pragma unroll
        for (int q = 0; q < 4; q++) {
            uint4 pk;
            pk.x = h2u(__floats2half2_rn(r0[2 * q].x, r0[2 * q].y));
            pk.y = h2u(__floats2half2_rn(r0[2 * q].z, r0[2 * q].w));
            pk.z = h2u(__floats2half2_rn(r0[2 * q + 1].x, r0[2 * q + 1].y));
            pk.w = h2u(__floats2half2_rn(r0[2 * q + 1].z, r0[2 * q + 1].w));
            *(uint4*)&u_sh[(2 * ipair) * 264 + seg * 32 + q * 8] = pk;
            uint4 pk1;
            pk1.x = h2u(__floats2half2_rn(r1[2 * q].x, r1[2 * q].y));
            pk1.y = h2u(__floats2half2_rn(r1[2 * q].z, r1[2 * q].w));
            pk1.z = h2u(__floats2half2_rn(r1[2 * q + 1].x, r1[2 * q + 1].y));
            pk1.w = h2u(__floats2half2_rn(r1[2 * q + 1].z, r1[2 * q + 1].w));
            *(uint4*)&u_sh[(2 * ipair + 1) * 264 + seg * 32 + q * 8] = pk1;
        }

        // u_t: half2(u[2ip][d], u[2ip+1][d]) at word (ipair + 4*seg) & 31 of row d
        const int colw = (ipair + 4 * seg) & 31;
        const float* f0 = (const float*)r0;
        const float* f1 = (const float*)r1;
#pragma unroll
        for (int k = 0; k < 32; k++) {
            const int d = seg * 32 + k;
            ((__half2*)&u_t[d * 66])[colw] = __floats2half2_rn(f0[k], f1[k]);
        }
    }
    __syncthreads();

    // ---- logits mma: L[i,n] = sum_d u[i,d] * w~[n,d]
    // warp w: m-tile mt = w>>1 (i rows 16mt..16mt+15), n-half h = w&1 (2 n-tiles)
    {
        const int mt = w >> 1, h = w & 1;
        float f[2][4];
#pragma unroll
        for (int nt = 0; nt < 2; nt++)
#pragma unroll
            for (int r = 0; r < 4; r++) f[nt][r] = 0.f;

#pragma unroll
        for (int ks = 0; ks < 16; ks++) {
            uint32_t a[4];
            a[0] = *(const uint32_t*)&u_sh[(16 * mt + g) * 264 + (8 * ks + tig) * 2];
            a[1] = *(const uint32_t*)&u_sh[(16 * mt + 8 + g) * 264 + (8 * ks + tig) * 2];
            a[2] = *(const uint32_t*)&u_sh[(16 * mt + g) * 264 + (8 * ks + tig + 4) * 2];
            a[3] = *(const uint32_t*)&u_sh[(16 * mt + 8 + g) * 264 + (8 * ks + tig + 4) * 2];
#pragma unroll
            for (int nt = 0; nt < 2; nt++) {
                const int n0 = h * 16 + nt * 8;
                uint32_t bb[2];
                bb[0] = *(const uint32_t*)&w_sh[(n0 + g) * 264 + (8 * ks + tig) * 2];
                bb[1] = *(const uint32_t*)&w_sh[(n0 + g) * 264 + (8 * ks + tig + 4) * 2];
                mma_f16(f[nt], a, bb);
            }
        }
#pragma unroll
        for (int nt = 0; nt < 2; nt++) {
            const int n0 = h * 16 + nt * 8 + 2 * tig;
            *(float2*)&L_sh[(16 * mt + g) * 34 + n0] = make_float2(f[nt][0], f[nt][1]);
            *(float2*)&L_sh[(16 * mt + 8 + g) * 34 + n0] = make_float2(f[nt][2], f[nt][3]);
        }
    }
    __syncthreads();

    // ---- softmax over n (lane = n); warp w handles i rows 8w..8w+7
#pragma unroll
    for (int r8 = 0; r8 < 8; r8++) {
        const int r = w * 8 + r8;
        const float val = L_sh[r * 34 + l];
        float mx = val;
#pragma unroll
        for (int off = 16; off; off >>= 1) mx = fmaxf(mx, __shfl_xor_sync(0xffffffffu, mx, off));
        const float e = __expf(val - mx);
        float s = e;
#pragma unroll
        for (int off = 16; off; off >>= 1) s += __shfl_xor_sync(0xffffffffu, s, off);
        c_sh[l * 72 + r] = __float2half_rn(e / s);   // c_sh[n][i]
    }
    __syncthreads();

    // ---- accumulation mma: V[d,n] = sum_i u_t[d,i] * c[n,i]
    // warp w: m-tiles 2w, 2w+1 (d rows 32w..32w+31); all 4 n-tiles; K=64 (4 steps)
    {
        float vfr[2][4][4];
#pragma unroll
        for (int s = 0; s < 2; s++)
#pragma unroll
            for (int nt = 0; nt < 4; nt++)
#pragma unroll
                for (int r = 0; r < 4; r++) vfr[s][nt][r] = 0.f;

        const int sw = 4 * (w & 7);   // u_t col swizzle: all rows of this warp have d>>5 == w
#pragma unroll
        for (int ks = 0; ks < 4; ks++) {
            const int kw0 = 8 * ks + tig, kw1 = kw0 + 4;
            uint32_t a[2][4];
#pragma unroll
            for (int s = 0; s < 2; s++) {
                const int dr0 = 32 * w + 16 * s + g;
                a[s][0] = *(const uint32_t*)&u_t[dr0 * 66 + (((kw0 + sw) & 31) << 1)];
                a[s][1] = *(const uint32_t*)&u_t[(dr0 + 8) * 66 + (((kw0 + sw) & 31) << 1)];
                a[s][2] = *(const uint32_t*)&u_t[dr0 * 66 + (((kw1 + sw) & 31) << 1)];
                a[s][3] = *(const uint32_t*)&u_t[(dr0 + 8) * 66 + (((kw1 + sw) & 31) << 1)];
            }
#pragma unroll
            for (int nt = 0; nt < 4; nt++) {
                uint32_t bb[2];
                bb[0] = *(const uint32_t*)&c_sh[(8 * nt + g) * 72 + (8 * ks + tig) * 2];
                bb[1] = *(const uint32_t*)&c_sh[(8 * nt + g) * 72 + (8 * ks + tig + 4) * 2];
                mma_f16(vfr[0][nt], a[0], bb);
                mma_f16(vfr[1][nt], a[1], bb);
            }
        }

        // store: frag (r0,r1) at (d, n0),(d, n0+1); (r2,r3) at d+8
        float* vp = g_vpart + (((size_t)b * CH + chunk) * NC) * ID;
#pragma unroll
        for (int s = 0; s < 2; s++) {
            const int d0 = 32 * w + 16 * s + g;
#pragma unroll
            for (int nt = 0; nt < 4; nt++) {
                const int n0 = 8 * nt + 2 * tig;
                vp[(size_t)n0 * ID + d0] = vfr[s][nt][0];
                vp[(size_t)(n0 + 1) * ID + d0] = vfr[s][nt][1];
                vp[(size_t)n0 * ID + d0 + 8] = vfr[s][nt][2];
                vp[(size_t)(n0 + 1) * ID + d0 + 8] = vfr[s][nt][3];
            }
        }
    }
}

// ---------------- launch ------------------------------------------------------
extern "C" void kernel_launch(void* const* d_in, const int* in_sizes, int n_in,
                              void* d_out, int out_size) {
    (void)in_sizes; (void)n_in; (void)out_size;
    const float* u = (const float*)d_in[0];   // [64, 1024, 256] fp32
    const float* W = (const float*)d_in[1];   // [2048, 256] fp32
    float* out = (float*)d_out;               // [64, 32, 64] fp32

    const int wbytes = DC * ID * (int)sizeof(float);  // 64 KB
    const int fbytes = 97792;                          // fused smem
    static int attr_done = 0;
    if (!attr_done) {
        cudaFuncSetAttribute(project_kernel<0>, cudaFuncAttributeMaxDynamicSharedMemorySize, wbytes);
        cudaFuncSetAttribute(project_kernel<1>, cudaFuncAttributeMaxDynamicSharedMemorySize, wbytes);
        cudaFuncSetAttribute(project_kernel<2>, cudaFuncAttributeMaxDynamicSharedMemorySize, wbytes);
        cudaFuncSetAttribute(fused_kernel, cudaFuncAttributeMaxDynamicSharedMemorySize, fbytes);
        attr_done = 1;
    }

    colsum_kernel<<<dim3(8, B), 256>>>(u);                       // s = sum_i u
    project_kernel<0><<<dim3(NC, 8), 256, wbytes>>>(W, out);     // o0 -> w~0
    fused_kernel<<<dim3(CH, B), 256, fbytes>>>(u);               // iter 1 -> v1
    project_kernel<1><<<dim3(NC, 8), 256, wbytes>>>(W, out);     // o1 -> w~1
    fused_kernel<<<dim3(CH, B), 256, fbytes>>>(u);               // iter 2 -> v2
    project_kernel<2><<<dim3(NC, 8), 256, wbytes>>>(W, out);     // squash -> out
}